// round 8
// baseline (speedup 1.0000x reference)
#include <cuda_runtime.h>
#include <cuda_fp16.h>
#include <cstdint>

#define NB    4
#define NC    64
#define NHEAD 8
#define HD    8
#define NWID  128
#define NH    128
#define NTOK  256
#define HWSZ  (NH*NWID)
#define NTHR  256
#define VPAD  264

typedef uint32_t u32;

__device__ __forceinline__ float ex2f(float x) {
    float y; asm("ex2.approx.f32 %0, %1;" : "=f"(y) : "f"(x)); return y;
}
__device__ __forceinline__ u32 totf(float x) {
    u32 r; asm("cvt.rna.tf32.f32 %0, %1;" : "=r"(r) : "f"(x)); return r;
}
// pack {lo, hi} floats -> f16x2 (cvt d,a,b puts b in low half)
__device__ __forceinline__ u32 cvt2h(float lo, float hi) {
    u32 r; asm("cvt.rn.f16x2.f32 %0, %1, %2;" : "=r"(r) : "f"(hi), "f"(lo)); return r;
}
__device__ __forceinline__ void mmatf(float c[4], const u32 a[4], u32 b0, u32 b1) {
    asm volatile("mma.sync.aligned.m16n8k8.row.col.f32.tf32.tf32.f32 "
        "{%0,%1,%2,%3},{%4,%5,%6,%7},{%8,%9},{%0,%1,%2,%3};"
        : "+f"(c[0]), "+f"(c[1]), "+f"(c[2]), "+f"(c[3])
        : "r"(a[0]), "r"(a[1]), "r"(a[2]), "r"(a[3]), "r"(b0), "r"(b1));
}
__device__ __forceinline__ void mma16(float c[4], const u32 a[4], u32 b0, u32 b1) {
    asm volatile("mma.sync.aligned.m16n8k16.row.col.f32.f16.f16.f32 "
        "{%0,%1,%2,%3},{%4,%5,%6,%7},{%8,%9},{%0,%1,%2,%3};"
        : "+f"(c[0]), "+f"(c[1]), "+f"(c[2]), "+f"(c[3])
        : "r"(a[0]), "r"(a[1]), "r"(a[2]), "r"(a[3]), "r"(b0), "r"(b1));
}

__global__ void __launch_bounds__(NTHR, 3) lepe_attn_tf32_kernel(
    const float* __restrict__ temp,     // (B, 3, C, H, W)
    const float* __restrict__ conv_w,   // (C, 1, 3, 3)
    const float* __restrict__ conv_b,   // (C,)
    float* __restrict__ out)            // (B, H*W, C)
{
    const int blk  = blockIdx.x;            // b*256 + head*32 + wp
    const int wp   = blk & 31;              // window pair -> cols 4wp..4wp+3
    const int head = (blk >> 5) & 7;
    const int b    = blk >> 8;
    const int t    = threadIdx.x;
    const int cbase = head * HD;

    __shared__ uint2 Kp[2 * NTOK][4];                 // tf32 K pairs {d, d+4}   16KB
    __shared__ union {
        uint2  Qp[2 * NTOK][4];                       // tf32 Q pairs (load/Afrag phase)
        __half Osm[2 * NTOK][12];                     // attn out (epilogue phase)
    } QO;                                             // 16KB
    __shared__ __half Vt[2][HD][VPAD];                // d-major V (f16)          8.4KB
    __shared__ float  Wc[HD][9];
    __shared__ float  Bc[HD];

    // ---------------- load phase: gather strips, convert, stage ----------------
    {
        const float qsc = 0.35355339059327373f * 1.4426950408889634f; // hd^-.5*log2e
        const int row = t & 127;
        const int uh  = t >> 7;                       // 0/1: which 6 of 12 units
        const int u0  = uh * 6;
#pragma unroll
        for (int uu = 0; uu < 6; uu++) {
            const int u = u0 + uu;
            const int tensor = u >> 2;                // 0=Q 1=K 2=V
            const int j = u & 3;                      // d pair {j, j+4}
            const float* g = temp + ((size_t)((b * 3 + tensor) * NC + cbase + j)) * HWSZ
                                  + row * NWID + 4 * wp;
            const float4 lo4 = *(const float4*)g;             // d = j,  4 pixels
            const float4 hi4 = *(const float4*)(g + 4 * HWSZ);// d = j+4
            const float lp[4] = {lo4.x, lo4.y, lo4.z, lo4.w};
            const float hp[4] = {hi4.x, hi4.y, hi4.z, hi4.w};
            if (tensor == 0) {
#pragma unroll
                for (int p = 0; p < 4; p++) {
                    const int tok = (p >> 1) * NTOK + 2 * row + (p & 1);
                    QO.Qp[tok][j] = make_uint2(totf(lp[p] * qsc), totf(hp[p] * qsc));
                }
            } else if (tensor == 1) {
#pragma unroll
                for (int p = 0; p < 4; p++) {
                    const int tok = (p >> 1) * NTOK + 2 * row + (p & 1);
                    Kp[tok][j] = make_uint2(totf(lp[p]), totf(hp[p]));
                }
            } else {
#pragma unroll
                for (int w2 = 0; w2 < 2; w2++) {
                    *(__half2*)&Vt[w2][j][2 * row]     = __floats2half2_rn(lp[2*w2], lp[2*w2+1]);
                    *(__half2*)&Vt[w2][j + 4][2 * row] = __floats2half2_rn(hp[2*w2], hp[2*w2+1]);
                }
            }
        }
        if (t < HD * 9) ((float*)Wc)[t] = conv_w[cbase * 9 + t];
        if (t >= 96 && t < 96 + HD) Bc[t - 96] = conv_b[cbase + (t - 96)];
    }
    __syncthreads();

    // ---------------- flash attention: warp = 64 queries of one window ----------------
    const int wid = t >> 5, l = t & 31;
    const int w2 = wid >> 2, qb = wid & 3;
    const int qr = l >> 2;                  // l/4
    const int jj = l & 3;
    const int lc = jj * 2;
    const int tb = w2 * NTOK;

    u32 A[4][4];
#pragma unroll
    for (int mt = 0; mt < 4; mt++) {
        const int q0 = tb + qb * 64 + mt * 16 + qr;
        const uint2 x = QO.Qp[q0][jj];
        const uint2 y = QO.Qp[q0 + 8][jj];
        A[mt][0] = x.x; A[mt][1] = y.x; A[mt][2] = x.y; A[mt][3] = y.y;
    }
    __syncthreads();    // Qp reads complete -> QO region reusable as Osm

    float O[4][4];
    float sp[4][2];
#pragma unroll
    for (int mt = 0; mt < 4; mt++) {
        O[mt][0] = O[mt][1] = O[mt][2] = O[mt][3] = 0.0f;
        sp[mt][0] = sp[mt][1] = 0.0f;
    }

#pragma unroll 1
    for (int c = 0; c < 16; c++) {
        const int key0 = c * 16;
        const uint2 kb0 = Kp[tb + key0 + qr][jj];        // keys key0..+7
        const uint2 kb1 = Kp[tb + key0 + 8 + qr][jj];    // keys key0+8..+15
        const u32 bv0 = *(const u32*)&Vt[w2][qr][key0 + lc];
        const u32 bv1 = *(const u32*)&Vt[w2][qr][key0 + 8 + lc];

#pragma unroll
        for (int mt = 0; mt < 4; mt++) {
            float D0[4] = {0, 0, 0, 0}, D1[4] = {0, 0, 0, 0};
            mmatf(D0, A[mt], kb0.x, kb0.y);
            mmatf(D1, A[mt], kb1.x, kb1.y);

            const float e00 = ex2f(D0[0]), e01 = ex2f(D0[1]);
            const float e02 = ex2f(D0[2]), e03 = ex2f(D0[3]);
            const float e10 = ex2f(D1[0]), e11 = ex2f(D1[1]);
            const float e12 = ex2f(D1[2]), e13 = ex2f(D1[3]);

            sp[mt][0] += (e00 + e01) + (e10 + e11);
            sp[mt][1] += (e02 + e03) + (e12 + e13);

            u32 pa[4];
            pa[0] = cvt2h(e00, e01);
            pa[1] = cvt2h(e02, e03);
            pa[2] = cvt2h(e10, e11);
            pa[3] = cvt2h(e12, e13);

            mma16(O[mt], pa, bv0, bv1);
        }
    }

    // ---------------- normalize + stage (f16) ----------------
#pragma unroll
    for (int mt = 0; mt < 4; mt++) {
        float s0 = sp[mt][0];
        s0 += __shfl_xor_sync(0xffffffffu, s0, 1);
        s0 += __shfl_xor_sync(0xffffffffu, s0, 2);
        float s1 = sp[mt][1];
        s1 += __shfl_xor_sync(0xffffffffu, s1, 1);
        s1 += __shfl_xor_sync(0xffffffffu, s1, 2);
        const float i0 = 1.0f / s0, i1 = 1.0f / s1;
        const int q0 = tb + qb * 64 + mt * 16 + qr;
        *(__half2*)&QO.Osm[q0][lc]     = __floats2half2_rn(O[mt][0] * i0, O[mt][1] * i0);
        *(__half2*)&QO.Osm[q0 + 8][lc] = __floats2half2_rn(O[mt][2] * i1, O[mt][3] * i1);
    }
    __syncthreads();

    // ---------------- LePE depthwise 3x3 conv + add + store ----------------
    {
        const int row = t & 127;
        const int ww2 = t >> 7;
        const int win = wp * 2 + ww2;
        float r0[HD], r1[HD];
#pragma unroll
        for (int d = 0; d < HD; d++) { r0[d] = Bc[d]; r1[d] = Bc[d]; }
#pragma unroll
        for (int dh = -1; dh <= 1; dh++) {
            const int hh = row + dh;
            if (hh < 0 || hh >= NH) continue;
            const int kkr = (dh + 1) * 3;
#pragma unroll
            for (int d = 0; d < HD; d++) {
                const float v0 = __half2float(Vt[ww2][d][2 * hh]);
                const float v1 = __half2float(Vt[ww2][d][2 * hh + 1]);
                r0[d] = fmaf(Wc[d][kkr + 1], v0, r0[d]);
                r0[d] = fmaf(Wc[d][kkr + 2], v1, r0[d]);
                r1[d] = fmaf(Wc[d][kkr + 0], v0, r1[d]);
                r1[d] = fmaf(Wc[d][kkr + 1], v1, r1[d]);
            }
        }
        const int n0 = ww2 * NTOK + 2 * row;
        const int pix0 = row * NWID + 2 * win;
        float* op0 = out + ((size_t)b * HWSZ + pix0) * NC + cbase;
        float* op1 = op0 + NC;
        float4 a0, a1, c0, c1;
        a0.x = __half2float(QO.Osm[n0][0]) + r0[0];
        a0.y = __half2float(QO.Osm[n0][1]) + r0[1];
        a0.z = __half2float(QO.Osm[n0][2]) + r0[2];
        a0.w = __half2float(QO.Osm[n0][3]) + r0[3];
        a1.x = __half2float(QO.Osm[n0][4]) + r0[4];
        a1.y = __half2float(QO.Osm[n0][5]) + r0[5];
        a1.z = __half2float(QO.Osm[n0][6]) + r0[6];
        a1.w = __half2float(QO.Osm[n0][7]) + r0[7];
        ((float4*)op0)[0] = a0; ((float4*)op0)[1] = a1;
        c0.x = __half2float(QO.Osm[n0 + 1][0]) + r1[0];
        c0.y = __half2float(QO.Osm[n0 + 1][1]) + r1[1];
        c0.z = __half2float(QO.Osm[n0 + 1][2]) + r1[2];
        c0.w = __half2float(QO.Osm[n0 + 1][3]) + r1[3];
        c1.x = __half2float(QO.Osm[n0 + 1][4]) + r1[4];
        c1.y = __half2float(QO.Osm[n0 + 1][5]) + r1[5];
        c1.z = __half2float(QO.Osm[n0 + 1][6]) + r1[6];
        c1.w = __half2float(QO.Osm[n0 + 1][7]) + r1[7];
        ((float4*)op1)[0] = c0; ((float4*)op1)[1] = c1;
    }
}

extern "C" void kernel_launch(void* const* d_in, const int* in_sizes, int n_in,
                              void* d_out, int out_size)
{
    const float* temp = (const float*)d_in[0];
    const float* cw   = (const float*)d_in[1];
    const float* cb   = (const float*)d_in[2];
    float* out        = (float*)d_out;
    lepe_attn_tf32_kernel<<<NB * NHEAD * 32, NTHR>>>(temp, cw, cb, out);
}

// round 9
// speedup vs baseline: 1.6856x; 1.6856x over previous
#include <cuda_runtime.h>
#include <cuda_fp16.h>
#include <cstdint>

#define NB    4
#define NC    64
#define NHEAD 8
#define HD    8
#define NWID  128
#define NH    128
#define HWSZ  (NH*NWID)
#define NWIN  64
#define NTOK  256
#define VPAD  264
#define SSTR  268            // prepass staging win stride (halves): 8B-aligned, 4-way max conflict

typedef uint32_t u32;

// window-major staging (f16): Qg/Kg = [B][head][win][tok][d], Vg = [B][head][win][d][tok]
__device__ __half Qg[(size_t)NB*NHEAD*NWIN*NTOK*HD];
__device__ __half Kg[(size_t)NB*NHEAD*NWIN*NTOK*HD];
__device__ __half Vg[(size_t)NB*NHEAD*NWIN*HD*NTOK];

__device__ __forceinline__ u32 cvt2h(float lo, float hi) {
    u32 r; asm("cvt.rn.f16x2.f32 %0, %1, %2;" : "=r"(r) : "f"(hi), "f"(lo)); return r;
}
__device__ __forceinline__ u32 hex2(u32 x) {
    u32 r; asm("ex2.approx.f16x2 %0, %1;" : "=r"(r) : "r"(x)); return r;
}
__device__ __forceinline__ float rcpf(float x) {
    float y; asm("rcp.approx.f32 %0, %1;" : "=f"(y) : "f"(x)); return y;
}
__device__ __forceinline__ void mma8(float c[4], u32 a0, u32 a1, u32 b0) {
    asm volatile("mma.sync.aligned.m16n8k8.row.col.f32.f16.f16.f32 "
        "{%0,%1,%2,%3},{%4,%5},{%6},{%0,%1,%2,%3};"
        : "+f"(c[0]), "+f"(c[1]), "+f"(c[2]), "+f"(c[3])
        : "r"(a0), "r"(a1), "r"(b0));
}
__device__ __forceinline__ void mma16(float c[4], const u32 a[4], u32 b0, u32 b1) {
    asm volatile("mma.sync.aligned.m16n8k16.row.col.f32.f16.f16.f32 "
        "{%0,%1,%2,%3},{%4,%5,%6,%7},{%8,%9},{%0,%1,%2,%3};"
        : "+f"(c[0]), "+f"(c[1]), "+f"(c[2]), "+f"(c[3])
        : "r"(a[0]), "r"(a[1]), "r"(a[2]), "r"(a[3]), "r"(b0), "r"(b1));
}

// ============ kernel 1: coalesced transpose (C,H,W) -> window-major f16 ============
__global__ void __launch_bounds__(256) prepass_kernel(const float* __restrict__ temp)
{
    __shared__ __half Ss[NWIN * SSTR];          // 34.3 KB
    const int blk    = blockIdx.x;              // ((b*3+tensor)*8+head)*8+rg
    const int rg     = blk & 7;
    const int head   = (blk >> 3) & 7;
    const int tensor = (blk >> 6) % 3;
    const int b      = (blk >> 6) / 3;
    const int r0     = rg * 16;
    const int t      = threadIdx.x;
    const float qsc  = 0.35355339059327373f * 1.4426950408889634f; // hd^-.5 * log2(e)

    const float* src = temp + ((size_t)((b * 3 + tensor) * NC + head * HD)) * HWSZ;

#pragma unroll
    for (int c = 0; c < 16; c++) {
        const int i4   = t + 256 * c;           // 4096 uint4 reads per CTA, coalesced
        const int d    = i4 >> 9;
        const int rloc = (i4 >> 5) & 15;
        const int wq   = i4 & 31;
        const float4 v = *(const float4*)(src + (size_t)d * HWSZ + (r0 + rloc) * NWID + 4 * wq);
        float f[4] = {v.x, v.y, v.z, v.w};
        if (tensor == 0) { f[0] *= qsc; f[1] *= qsc; f[2] *= qsc; f[3] *= qsc; }
#pragma unroll
        for (int p = 0; p < 4; p++) {
            const int win = 2 * wq + (p >> 1);
            const int wsp = p & 1;
            int off;
            if (tensor < 2) off = win * SSTR + (2 * rloc + wsp) * 8 + d;   // [tok][d]
            else            off = win * SSTR + d * 32 + 2 * rloc + wsp;    // [d][tok]
            Ss[off] = __float2half_rn(f[p]);
        }
    }
    __syncthreads();

    const size_t base = (size_t)(b * NHEAD + head) * NWIN * (NTOK * HD);
    if (tensor < 2) {
        __half* dst = (tensor == 0) ? Qg : Kg;
#pragma unroll
        for (int c = 0; c < 16; c++) {
            const int i2  = t + 256 * c;
            const int win = i2 >> 6;
            const int p   = i2 & 63;
            const uint2 val = *(const uint2*)&Ss[win * SSTR + p * 4];
            *(uint2*)&dst[base + (size_t)win * (NTOK * HD) + (size_t)(2 * r0) * HD + p * 4] = val;
        }
    } else {
#pragma unroll
        for (int c = 0; c < 16; c++) {
            const int i2  = t + 256 * c;
            const int win = i2 >> 6;
            const int d   = (i2 >> 3) & 7;
            const int p   = i2 & 7;
            const uint2 val = *(const uint2*)&Ss[win * SSTR + d * 32 + p * 4];
            *(uint2*)&Vg[base + (size_t)win * (HD * NTOK) + d * NTOK + 2 * r0 + p * 4] = val;
        }
    }
}

// ============ kernel 2: flash attention + LePE, coalesced staged input ============
__global__ void __launch_bounds__(256, 2) lepe_attn_kernel(
    const float* __restrict__ conv_w,
    const float* __restrict__ conv_b,
    float* __restrict__ out)
{
    const int blk  = blockIdx.x;                // (b*8+head)*32 + wp
    const int wp   = blk & 31;
    const int head = (blk >> 5) & 7;
    const int b    = blk >> 8;
    const int t    = threadIdx.x;
    const int cbase = head * HD;

    __shared__ __half Ksm[2 * NTOK][HD];                       // 8 KB
    __shared__ __align__(16) char qo_raw[2 * NTOK * 12 * 2];   // 12 KB: Qsm then Osm
    __shared__ __half Vt[2][HD][VPAD];                         // 8.25 KB
    __shared__ float  Wc[HD][9];
    __shared__ float  Bc[HD];
    __half (*Qsm)[HD] = (__half(*)[HD])qo_raw;
    __half (*Osm)[12] = (__half(*)[12])qo_raw;

    // ---- coalesced load of staged Q/K/V ----
    {
        const size_t chnk = ((size_t)(b * NHEAD + head) * NWIN + 2 * wp) * (NTOK * HD);
        const uint4* Qg4 = (const uint4*)(Qg + chnk);
        const uint4* Kg4 = (const uint4*)(Kg + chnk);
        const uint4* Vg4 = (const uint4*)(Vg + chnk);
#pragma unroll
        for (int c = 0; c < 2; c++) {
            const int i = t + 256 * c;          // 0..511
            *(uint4*)&Qsm[i][0] = Qg4[i];
            *(uint4*)&Ksm[i][0] = Kg4[i];
            const int w = i >> 8, d = (i >> 5) & 7, t8 = (i & 31) * 8;
            *(uint4*)&Vt[w][d][t8] = Vg4[i];
        }
        if (t < HD * 9) ((float*)Wc)[t] = conv_w[cbase * 9 + t];
        if (t >= 96 && t < 96 + HD) Bc[t - 96] = conv_b[cbase + (t - 96)];
    }
    __syncthreads();

    const int wid = t >> 5, l = t & 31;
    const int w2 = wid >> 2, qb = wid & 3;
    const int qr = l >> 2, jj = l & 3, lc = jj * 2;
    const int tb = w2 * NTOK;

    u32 A[4][2];
#pragma unroll
    for (int mt = 0; mt < 4; mt++) {
        const int q0 = tb + qb * 64 + mt * 16 + qr;
        A[mt][0] = *(const u32*)&Qsm[q0][lc];
        A[mt][1] = *(const u32*)&Qsm[q0 + 8][lc];
    }
    __syncthreads();       // Qsm consumed -> region becomes Osm

    float O[4][4], S[4][4];
#pragma unroll
    for (int mt = 0; mt < 4; mt++)
#pragma unroll
        for (int k = 0; k < 4; k++) { O[mt][k] = 0.0f; S[mt][k] = 0.0f; }

    const u32 H1 = 0x3C003C00u;   // f16x2 {1,1}

#pragma unroll 1
    for (int c = 0; c < 16; c++) {
        const int key0 = c * 16;
        const u32 kb0 = *(const u32*)&Ksm[tb + key0 + qr][lc];
        const u32 kb1 = *(const u32*)&Ksm[tb + key0 + 8 + qr][lc];
        const u32 bv0 = *(const u32*)&Vt[w2][qr][key0 + lc];
        const u32 bv1 = *(const u32*)&Vt[w2][qr][key0 + 8 + lc];

#pragma unroll
        for (int mt = 0; mt < 4; mt++) {
            float D0[4] = {0, 0, 0, 0}, D1[4] = {0, 0, 0, 0};
            mma8(D0, A[mt][0], A[mt][1], kb0);
            mma8(D1, A[mt][0], A[mt][1], kb1);
            u32 pa[4];
            pa[0] = hex2(cvt2h(D0[0], D0[1]));
            pa[1] = hex2(cvt2h(D0[2], D0[3]));
            pa[2] = hex2(cvt2h(D1[0], D1[1]));
            pa[3] = hex2(cvt2h(D1[2], D1[3]));
            mma16(O[mt], pa, bv0, bv1);   // P @ V
            mma16(S[mt], pa, H1, H1);     // row sums via ones-B
        }
    }

    // ---- normalize + stage f16 ----
#pragma unroll
    for (int mt = 0; mt < 4; mt++) {
        const float i0 = rcpf(S[mt][0]);
        const float i1 = rcpf(S[mt][2]);
        const int q0 = tb + qb * 64 + mt * 16 + qr;
        *(__half2*)&Osm[q0][lc]     = __floats2half2_rn(O[mt][0] * i0, O[mt][1] * i0);
        *(__half2*)&Osm[q0 + 8][lc] = __floats2half2_rn(O[mt][2] * i1, O[mt][3] * i1);
    }
    __syncthreads();

    // ---- LePE depthwise 3x3 conv + add + store ----
    {
        const int row = t & 127;
        const int ww2 = t >> 7;
        const int win = wp * 2 + ww2;
        float r0[HD], r1[HD];
#pragma unroll
        for (int d = 0; d < HD; d++) { r0[d] = Bc[d]; r1[d] = Bc[d]; }
#pragma unroll
        for (int dh = -1; dh <= 1; dh++) {
            const int hh = row + dh;
            if (hh < 0 || hh >= NH) continue;
            const int kkr = (dh + 1) * 3;
#pragma unroll
            for (int d = 0; d < HD; d++) {
                const float v0 = __half2float(Vt[ww2][d][2 * hh]);
                const float v1 = __half2float(Vt[ww2][d][2 * hh + 1]);
                r0[d] = fmaf(Wc[d][kkr + 1], v0, r0[d]);
                r0[d] = fmaf(Wc[d][kkr + 2], v1, r0[d]);
                r1[d] = fmaf(Wc[d][kkr + 0], v0, r1[d]);
                r1[d] = fmaf(Wc[d][kkr + 1], v1, r1[d]);
            }
        }
        const int n0 = ww2 * NTOK + 2 * row;
        const int pix0 = row * NWID + 2 * win;
        float* op0 = out + ((size_t)b * HWSZ + pix0) * NC + cbase;
        float* op1 = op0 + NC;
        float4 a0, a1, c0, c1;
        a0.x = __half2float(Osm[n0][0]) + r0[0];
        a0.y = __half2float(Osm[n0][1]) + r0[1];
        a0.z = __half2float(Osm[n0][2]) + r0[2];
        a0.w = __half2float(Osm[n0][3]) + r0[3];
        a1.x = __half2float(Osm[n0][4]) + r0[4];
        a1.y = __half2float(Osm[n0][5]) + r0[5];
        a1.z = __half2float(Osm[n0][6]) + r0[6];
        a1.w = __half2float(Osm[n0][7]) + r0[7];
        ((float4*)op0)[0] = a0; ((float4*)op0)[1] = a1;
        c0.x = __half2float(Osm[n0 + 1][0]) + r1[0];
        c0.y = __half2float(Osm[n0 + 1][1]) + r1[1];
        c0.z = __half2float(Osm[n0 + 1][2]) + r1[2];
        c0.w = __half2float(Osm[n0 + 1][3]) + r1[3];
        c1.x = __half2float(Osm[n0 + 1][4]) + r1[4];
        c1.y = __half2float(Osm[n0 + 1][5]) + r1[5];
        c1.z = __half2float(Osm[n0 + 1][6]) + r1[6];
        c1.w = __half2float(Osm[n0 + 1][7]) + r1[7];
        ((float4*)op1)[0] = c0; ((float4*)op1)[1] = c1;
    }
}

extern "C" void kernel_launch(void* const* d_in, const int* in_sizes, int n_in,
                              void* d_out, int out_size)
{
    const float* temp = (const float*)d_in[0];
    const float* cw   = (const float*)d_in[1];
    const float* cb   = (const float*)d_in[2];
    float* out        = (float*)d_out;
    prepass_kernel<<<NB * 3 * NHEAD * 8, 256>>>(temp);
    lepe_attn_kernel<<<NB * NHEAD * 32, 256>>>(cw, cb, out);
}

// round 14
// speedup vs baseline: 1.8435x; 1.0936x over previous
#include <cuda_runtime.h>
#include <cuda_fp16.h>
#include <cstdint>

#define NB    4
#define NC    64
#define NHEAD 8
#define HD    8
#define NWID  128
#define NH    128
#define HWSZ  (NH*NWID)
#define NWIN  64
#define NTOK  256
#define VPAD  264
#define PSTR  65             // prepass staging: 64 windows + 1 pad (2-way LDS conflicts max)

typedef uint32_t u32;

// window-major staging (f16): Qg/Kg = [B][head][win][tok][d], Vg = [B][head][win][d][tok]
__device__ __half Qg[(size_t)NB*NHEAD*NWIN*NTOK*HD];
__device__ __half Kg[(size_t)NB*NHEAD*NWIN*NTOK*HD];
__device__ __half Vg[(size_t)NB*NHEAD*NWIN*HD*NTOK];

__device__ __forceinline__ u32 cvt2h(float lo, float hi) {
    u32 r; asm("cvt.rn.f16x2.f32 %0, %1, %2;" : "=r"(r) : "f"(hi), "f"(lo)); return r;
}
__device__ __forceinline__ u32 hex2(u32 x) {
    u32 r; asm("ex2.approx.f16x2 %0, %1;" : "=r"(r) : "r"(x)); return r;
}
__device__ __forceinline__ float rcpf(float x) {
    float y; asm("rcp.approx.f32 %0, %1;" : "=f"(y) : "f"(x)); return y;
}
__device__ __forceinline__ void mma8(float c[4], u32 a0, u32 a1, u32 b0) {
    asm volatile("mma.sync.aligned.m16n8k8.row.col.f32.f16.f16.f32 "
        "{%0,%1,%2,%3},{%4,%5},{%6},{%0,%1,%2,%3};"
        : "+f"(c[0]), "+f"(c[1]), "+f"(c[2]), "+f"(c[3])
        : "r"(a0), "r"(a1), "r"(b0));
}
__device__ __forceinline__ void mma16(float c[4], const u32 a[4], u32 b0, u32 b1) {
    asm volatile("mma.sync.aligned.m16n8k16.row.col.f32.f16.f16.f32 "
        "{%0,%1,%2,%3},{%4,%5,%6,%7},{%8,%9},{%0,%1,%2,%3};"
        : "+f"(c[0]), "+f"(c[1]), "+f"(c[2]), "+f"(c[3])
        : "r"(a[0]), "r"(a[1]), "r"(a[2]), "r"(a[3]), "r"(b0), "r"(b1));
}

// ============ kernel 1: coalesced transpose (C,H,W) -> window-major f16 ============
__global__ void __launch_bounds__(256) prepass_kernel(const float* __restrict__ temp)
{
    __shared__ __half Ss[256 * PSTR];           // 33.3 KB, win-fastest
    const int blk    = blockIdx.x;              // ((b*3+tensor)*8+head)*8+rg
    const int rg     = blk & 7;
    const int head   = (blk >> 3) & 7;
    const int tensor = (blk >> 6) % 3;
    const int b      = (blk >> 6) / 3;
    const int r0     = rg * 16;
    const int t      = threadIdx.x;
    const float qsc  = (tensor == 0) ? 0.35355339059327373f * 1.4426950408889634f : 1.0f;

    const float* src = temp + ((size_t)((b * 3 + tensor) * NC + head * HD)) * HWSZ;

#pragma unroll
    for (int c = 0; c < 16; c++) {
        const int i4   = t + 256 * c;           // coalesced float4 reads
        const int d    = i4 >> 9;
        const int rloc = (i4 >> 5) & 15;
        const int wq   = i4 & 31;
        const float4 v = *(const float4*)(src + (size_t)d * HWSZ + (r0 + rloc) * NWID + 4 * wq);
        const float f[4] = {v.x * qsc, v.y * qsc, v.z * qsc, v.w * qsc};
#pragma unroll
        for (int p = 0; p < 4; p++) {
            const int win    = 2 * wq + (p >> 1);
            const int tokloc = 2 * rloc + (p & 1);
            const int x = (tensor < 2) ? (tokloc * 8 + d) : (d * 32 + tokloc);
            Ss[x * PSTR + win] = __float2half_rn(f[p]);   // lanes: consecutive win -> 1 wf
        }
    }
    __syncthreads();

    const size_t base = (size_t)(b * NHEAD + head) * NWIN * (NTOK * HD);
    if (tensor < 2) {
        __half* dst = (tensor == 0) ? Qg : Kg;
#pragma unroll
        for (int c = 0; c < 16; c++) {
            const int i2  = t + 256 * c;        // 4096 uint2 per CTA
            const int win = i2 >> 6;
            const int q   = i2 & 63;
            const int tokloc = q >> 1, j = q & 1;
            const int x = tokloc * 8 + 4 * j;
            const u32 a0 = __half_as_ushort(Ss[(x + 0) * PSTR + win]);
            const u32 a1 = __half_as_ushort(Ss[(x + 1) * PSTR + win]);
            const u32 a2 = __half_as_ushort(Ss[(x + 2) * PSTR + win]);
            const u32 a3 = __half_as_ushort(Ss[(x + 3) * PSTR + win]);
            uint2 val; val.x = a0 | (a1 << 16); val.y = a2 | (a3 << 16);
            *(uint2*)&dst[base + (size_t)win * (NTOK * HD) + (2 * r0 + tokloc) * 8 + 4 * j] = val;
        }
    } else {
#pragma unroll
        for (int c = 0; c < 16; c++) {
            const int i2  = t + 256 * c;
            const int win = i2 >> 6;
            const int q   = i2 & 63;
            const int d = q >> 3, m = q & 7;
            const int x = d * 32 + 4 * m;
            const u32 a0 = __half_as_ushort(Ss[(x + 0) * PSTR + win]);
            const u32 a1 = __half_as_ushort(Ss[(x + 1) * PSTR + win]);
            const u32 a2 = __half_as_ushort(Ss[(x + 2) * PSTR + win]);
            const u32 a3 = __half_as_ushort(Ss[(x + 3) * PSTR + win]);
            uint2 val; val.x = a0 | (a1 << 16); val.y = a2 | (a3 << 16);
            *(uint2*)&Vg[base + (size_t)win * (HD * NTOK) + d * NTOK + 2 * r0 + 4 * m] = val;
        }
    }
}

// ============ kernel 2: flash attention + LePE ============
__global__ void __launch_bounds__(256, 3) lepe_attn_kernel(
    const float* __restrict__ conv_w,
    const float* __restrict__ conv_b,
    float* __restrict__ out)
{
    const int blk  = blockIdx.x;                // (b*8+head)*32 + wp
    const int wp   = blk & 31;
    const int head = (blk >> 5) & 7;
    const int b    = blk >> 8;
    const int t    = threadIdx.x;
    const int cbase = head * HD;

    __shared__ __half Ksm[2 * NTOK][HD];                       // 8 KB
    __shared__ __align__(16) char qo_raw[2 * NTOK * 12 * 2];   // 12 KB: Qsm then Osm
    __shared__ __half Vt[2][HD][VPAD];                         // 8.25 KB
    __shared__ float  Wc[HD][9];
    __shared__ float  Bc[HD];
    __half (*Qsm)[HD] = (__half(*)[HD])qo_raw;
    __half (*Osm)[12] = (__half(*)[12])qo_raw;

    // ---- coalesced load of staged Q/K/V ----
    {
        const size_t chnk = ((size_t)(b * NHEAD + head) * NWIN + 2 * wp) * (NTOK * HD);
        const uint4* Qg4 = (const uint4*)(Qg + chnk);
        const uint4* Kg4 = (const uint4*)(Kg + chnk);
        const uint4* Vg4 = (const uint4*)(Vg + chnk);
#pragma unroll
        for (int c = 0; c < 2; c++) {
            const int i = t + 256 * c;          // 0..511
            *(uint4*)&Qsm[i][0] = Qg4[i];
            *(uint4*)&Ksm[i][0] = Kg4[i];
            const int w = i >> 8, d = (i >> 5) & 7, t8 = (i & 31) * 8;
            *(uint4*)&Vt[w][d][t8] = Vg4[i];
        }
        if (t < HD * 9) ((float*)Wc)[t] = conv_w[cbase * 9 + t];
        if (t >= 96 && t < 96 + HD) Bc[t - 96] = conv_b[cbase + (t - 96)];
    }
    __syncthreads();

    const int wid = t >> 5, l = t & 31;
    const int w2 = wid >> 2, qb = wid & 3;
    const int qr = l >> 2, jj = l & 3, lc = jj * 2;
    const int tb = w2 * NTOK;

    u32 A[4][2];
#pragma unroll
    for (int mt = 0; mt < 4; mt++) {
        const int q0 = tb + qb * 64 + mt * 16 + qr;
        A[mt][0] = *(const u32*)&Qsm[q0][lc];
        A[mt][1] = *(const u32*)&Qsm[q0 + 8][lc];
    }
    __syncthreads();       // Qsm consumed -> region becomes Osm

    float O[4][4], S[4][4];
#pragma unroll
    for (int mt = 0; mt < 4; mt++)
#pragma unroll
        for (int k = 0; k < 4; k++) { O[mt][k] = 0.0f; S[mt][k] = 0.0f; }

    const u32 H1 = 0x3C003C00u;   // f16x2 {1,1}

    // 1-deep software pipeline over the 16 key blocks
    u32 kb0 = *(const u32*)&Ksm[tb + qr][lc];
    u32 kb1 = *(const u32*)&Ksm[tb + 8 + qr][lc];
    u32 bv0 = *(const u32*)&Vt[w2][qr][lc];
    u32 bv1 = *(const u32*)&Vt[w2][qr][8 + lc];

#pragma unroll 1
    for (int c = 0; c < 16; c++) {
        u32 nk0, nk1, nv0, nv1;
        if (c < 15) {
            const int key1 = (c + 1) * 16;
            nk0 = *(const u32*)&Ksm[tb + key1 + qr][lc];
            nk1 = *(const u32*)&Ksm[tb + key1 + 8 + qr][lc];
            nv0 = *(const u32*)&Vt[w2][qr][key1 + lc];
            nv1 = *(const u32*)&Vt[w2][qr][key1 + 8 + lc];
        }
#pragma unroll
        for (int mt = 0; mt < 4; mt++) {
            float D0[4] = {0, 0, 0, 0}, D1[4] = {0, 0, 0, 0};
            mma8(D0, A[mt][0], A[mt][1], kb0);
            mma8(D1, A[mt][0], A[mt][1], kb1);
            u32 pa[4];
            pa[0] = hex2(cvt2h(D0[0], D0[1]));
            pa[1] = hex2(cvt2h(D0[2], D0[3]));
            pa[2] = hex2(cvt2h(D1[0], D1[1]));
            pa[3] = hex2(cvt2h(D1[2], D1[3]));
            mma16(O[mt], pa, bv0, bv1);   // P @ V
            mma16(S[mt], pa, H1, H1);     // exact f32 row sums
        }
        kb0 = nk0; kb1 = nk1; bv0 = nv0; bv1 = nv1;
    }

    // ---- normalize + stage f16 ----
#pragma unroll
    for (int mt = 0; mt < 4; mt++) {
        const float i0 = rcpf(S[mt][0]);
        const float i1 = rcpf(S[mt][2]);
        const int q0 = tb + qb * 64 + mt * 16 + qr;
        *(__half2*)&Osm[q0][lc]     = __floats2half2_rn(O[mt][0] * i0, O[mt][1] * i0);
        *(__half2*)&Osm[q0 + 8][lc] = __floats2half2_rn(O[mt][2] * i1, O[mt][3] * i1);
    }
    __syncthreads();

    // ---- LePE depthwise 3x3 conv + add + store ----
    {
        const int row = t & 127;
        const int ww2 = t >> 7;
        const int win = wp * 2 + ww2;
        float r0[HD], r1[HD];
#pragma unroll
        for (int d = 0; d < HD; d++) { r0[d] = Bc[d]; r1[d] = Bc[d]; }
#pragma unroll
        for (int dh = -1; dh <= 1; dh++) {
            const int hh = row + dh;
            if (hh < 0 || hh >= NH) continue;
            const int kkr = (dh + 1) * 3;
#pragma unroll
            for (int d = 0; d < HD; d++) {
                const float v0 = __half2float(Vt[ww2][d][2 * hh]);
                const float v1 = __half2float(Vt[ww2][d][2 * hh + 1]);
                r0[d] = fmaf(Wc[d][kkr + 1], v0, r0[d]);
                r0[d] = fmaf(Wc[d][kkr + 2], v1, r0[d]);
                r1[d] = fmaf(Wc[d][kkr + 0], v0, r1[d]);
                r1[d] = fmaf(Wc[d][kkr + 1], v1, r1[d]);
            }
        }
        const int n0 = ww2 * NTOK + 2 * row;
        const int pix0 = row * NWID + 2 * win;
        float* op0 = out + ((size_t)b * HWSZ + pix0) * NC + cbase;
        float* op1 = op0 + NC;
        float4 a0, a1, c0, c1;
        a0.x = __half2float(Osm[n0][0]) + r0[0];
        a0.y = __half2float(Osm[n0][1]) + r0[1];
        a0.z = __half2float(Osm[n0][2]) + r0[2];
        a0.w = __half2float(Osm[n0][3]) + r0[3];
        a1.x = __half2float(Osm[n0][4]) + r0[4];
        a1.y = __half2float(Osm[n0][5]) + r0[5];
        a1.z = __half2float(Osm[n0][6]) + r0[6];
        a1.w = __half2float(Osm[n0][7]) + r0[7];
        ((float4*)op0)[0] = a0; ((float4*)op0)[1] = a1;
        c0.x = __half2float(Osm[n0 + 1][0]) + r1[0];
        c0.y = __half2float(Osm[n0 + 1][1]) + r1[1];
        c0.z = __half2float(Osm[n0 + 1][2]) + r1[2];
        c0.w = __half2float(Osm[n0 + 1][3]) + r1[3];
        c1.x = __half2float(Osm[n0 + 1][4]) + r1[4];
        c1.y = __half2float(Osm[n0 + 1][5]) + r1[5];
        c1.z = __half2float(Osm[n0 + 1][6]) + r1[6];
        c1.w = __half2float(Osm[n0 + 1][7]) + r1[7];
        ((float4*)op1)[0] = c0; ((float4*)op1)[1] = c1;
    }
}

extern "C" void kernel_launch(void* const* d_in, const int* in_sizes, int n_in,
                              void* d_out, int out_size)
{
    const float* temp = (const float*)d_in[0];
    const float* cw   = (const float*)d_in[1];
    const float* cb   = (const float*)d_in[2];
    float* out        = (float*)d_out;
    prepass_kernel<<<NB * 3 * NHEAD * 8, 256>>>(temp);
    lepe_attn_kernel<<<NB * NHEAD * 32, 256>>>(cw, cb, out);
}